// round 1
// baseline (speedup 1.0000x reference)
#include <cuda_runtime.h>
#include <math.h>

// ---------------------------------------------------------------------------
// PathGuidedAggregator: S=8192 nodes x P=16 paths x K=16 endpoints, D=128, H=64
// Inputs (metadata order):
//  0 entity_embeds [N,D] f32
//  1 W1 [D,H] f32
//  2 b1 [H] f32
//  3 W2 [H,1] f32
//  4 b2 [1] f32
//  5 sparse_ids [S] i32
//  6 endpoint_ids [S,P,K] i32
//  7 endpoint_mask [S,P,K] bool (dtype detected at runtime: u8 / i32 / f32)
// Output: [N,D] f32 (zeros except rows sparse_ids)
// ---------------------------------------------------------------------------

#define DD 128
#define PP 16
#define KK 16
#define HH 64

__device__ int g_mask_mode; // 0 = uint8, 1 = int32, 2 = float32

__global__ void detect_mask_kernel(const unsigned int* __restrict__ w) {
    __shared__ int f_gt1, f_one;
    if (threadIdx.x == 0) { f_gt1 = 0; f_one = 0; }
    __syncthreads();
    unsigned v = w[threadIdx.x];
    if (v == 0x3F800000u)      atomicOr(&f_one, 1);
    else if (v > 1u)           atomicOr(&f_gt1, 1);
    __syncthreads();
    if (threadIdx.x == 0)
        g_mask_mode = f_gt1 ? 0 : (f_one ? 2 : 1);
}

// ---- packed f32x2 helpers (sm_100+) ---------------------------------------
__device__ __forceinline__ unsigned long long pack2(float x, float y) {
    unsigned long long r;
    asm("mov.b64 %0, {%1, %2};" : "=l"(r) : "f"(x), "f"(y));
    return r;
}
__device__ __forceinline__ float2 unpack2(unsigned long long v) {
    float2 r;
    asm("mov.b64 {%0, %1}, %2;" : "=f"(r.x), "=f"(r.y) : "l"(v));
    return r;
}
__device__ __forceinline__ void fma2(unsigned long long& acc,
                                     unsigned long long a,
                                     unsigned long long b) {
    asm("fma.rn.f32x2 %0, %1, %2, %0;" : "+l"(acc) : "l"(a), "l"(b));
}

// Dynamic SMEM layout (floats):
//   sW1   [0      .. 8192)   W1 [d][j], 32 KB
//   sAgg  [8192   .. 10240)  [16][128]
//   sPart [10240  .. 12288)  (ull[2][512]) partial h, 8 KB
//   sW2   [12288  .. 12352)
//   sb1   [12352  .. 12416)
//   sWgt  [12416  .. 12432)
//   sVal  [12432  .. 12448)  (int)
static const int SMEM_FLOATS = 12448;

__global__ void __launch_bounds__(512)
pga_kernel(const float* __restrict__ E, const float* __restrict__ W1,
           const float* __restrict__ b1, const float* __restrict__ W2,
           const float* __restrict__ b2, const int* __restrict__ sids,
           const int* __restrict__ eids, const void* __restrict__ maskp,
           float* __restrict__ out, int S) {
    extern __shared__ float smem[];
    float* sW1  = smem;
    float* sAgg = smem + 8192;
    unsigned long long* sPart = (unsigned long long*)(smem + 10240);
    float* sW2  = smem + 12288;
    float* sb1  = smem + 12352;
    float* sWgt = smem + 12416;
    int*   sVal = (int*)(smem + 12432);

    const int t = threadIdx.x;
    const int lane = t & 31;
    const int warp = t >> 5;

    for (int i = t; i < DD * HH; i += 512) sW1[i] = W1[i];
    if (t < HH) { sW2[t] = W2[t]; sb1[t] = b1[t]; }
    const int mode = g_mask_mode;
    const float bias2 = b2[0];
    __syncthreads();

    for (int s = blockIdx.x; s < S; s += gridDim.x) {
        // ---------------- Phase A: gather (warp p <-> path p) --------------
        {
            const int p = warp;
            const int base = (s * PP + p) * KK;
            const int4* ip = (const int4*)(eids + base);
            int4 i0 = __ldg(ip + 0), i1 = __ldg(ip + 1);
            int4 i2 = __ldg(ip + 2), i3 = __ldg(ip + 3);

            unsigned mb = 0;
            if (mode == 0) {
                uint4 mv = __ldg((const uint4*)((const unsigned char*)maskp + base));
                unsigned wds[4] = {mv.x, mv.y, mv.z, mv.w};
                #pragma unroll
                for (int q = 0; q < 4; q++)
                    #pragma unroll
                    for (int b = 0; b < 4; b++)
                        mb |= (((wds[q] >> (8 * b)) & 0xFFu) ? 1u : 0u) << (q * 4 + b);
            } else if (mode == 1) {
                const int4* m4 = (const int4*)((const int*)maskp + base);
                #pragma unroll
                for (int q = 0; q < 4; q++) {
                    int4 mv = __ldg(m4 + q);
                    mb |= (mv.x ? 1u : 0u) << (q * 4 + 0);
                    mb |= (mv.y ? 1u : 0u) << (q * 4 + 1);
                    mb |= (mv.z ? 1u : 0u) << (q * 4 + 2);
                    mb |= (mv.w ? 1u : 0u) << (q * 4 + 3);
                }
            } else {
                const float4* m4 = (const float4*)((const float*)maskp + base);
                #pragma unroll
                for (int q = 0; q < 4; q++) {
                    float4 mv = __ldg(m4 + q);
                    mb |= (mv.x != 0.f ? 1u : 0u) << (q * 4 + 0);
                    mb |= (mv.y != 0.f ? 1u : 0u) << (q * 4 + 1);
                    mb |= (mv.z != 0.f ? 1u : 0u) << (q * 4 + 2);
                    mb |= (mv.w != 0.f ? 1u : 0u) << (q * 4 + 3);
                }
            }
            const int cnt = __popc(mb);

            const float4* E4 = (const float4*)E;
            float4 acc = make_float4(0.f, 0.f, 0.f, 0.f);
            const int idk[16] = {i0.x, i0.y, i0.z, i0.w, i1.x, i1.y, i1.z, i1.w,
                                 i2.x, i2.y, i2.z, i2.w, i3.x, i3.y, i3.z, i3.w};
            #pragma unroll
            for (int k = 0; k < KK; k++) {
                if (mb & (1u << k)) {
                    float4 v = __ldg(E4 + idk[k] * (DD / 4) + lane);
                    acc.x += v.x; acc.y += v.y; acc.z += v.z; acc.w += v.w;
                }
            }
            const float inv = 1.f / (float)(cnt > 0 ? cnt : 1);
            float4 a = make_float4(acc.x * inv, acc.y * inv, acc.z * inv, acc.w * inv);
            ((float4*)(sAgg + p * DD))[lane] = a;
            if (lane == 0) sVal[p] = (cnt > 0);
        }
        __syncthreads();

        // ------------- Phase B: split-K GEMM  h[p][j] partials -------------
        // thread: set = t>>8 (d-half), p = (t>>4)&15, js = t&15 (j = 4*js..+3)
        {
            const int set = t >> 8;
            const int p   = (t >> 4) & 15;
            const int js  = t & 15;
            const float* ap = sAgg + p * DD + set * 64;
            const float* wp = sW1 + (set * 64) * HH + js * 4;
            unsigned long long h01 = 0ull, h23 = 0ull; // {+0,+0} bit pattern
            #pragma unroll
            for (int dd = 0; dd < 64; dd += 4) {
                float4 a4 = *(const float4*)(ap + dd);
                float av[4] = {a4.x, a4.y, a4.z, a4.w};
                #pragma unroll
                for (int r = 0; r < 4; r++) {
                    unsigned long long aa = pack2(av[r], av[r]);
                    ulonglong2 wv = *(const ulonglong2*)(wp + (dd + r) * HH);
                    fma2(h01, aa, wv.x);
                    fma2(h23, aa, wv.y);
                }
            }
            sPart[set * 512 + p * 32 + js * 2 + 0] = h01;
            sPart[set * 512 + p * 32 + js * 2 + 1] = h23;
        }
        __syncthreads();

        // ------- Phase C: combine halves, bias+relu, dot W2, sigmoid -------
        // thread t = p*32 + jj handles j = {2jj, 2jj+1}; warp == path
        {
            const int p = warp;
            const int jj = lane;
            float2 u = unpack2(sPart[t]);
            float2 v = unpack2(sPart[512 + t]);
            float h0 = fmaxf(u.x + v.x + sb1[2 * jj],     0.f);
            float h1 = fmaxf(u.y + v.y + sb1[2 * jj + 1], 0.f);
            float hw = h0 * sW2[2 * jj] + h1 * sW2[2 * jj + 1];
            #pragma unroll
            for (int o = 16; o; o >>= 1) hw += __shfl_xor_sync(0xffffffffu, hw, o);
            if (lane == 0) {
                float x = hw + bias2;
                float w = 1.f / (1.f + expf(-x));
                sWgt[p] = sVal[p] ? w : 0.f;
            }
        }
        __syncthreads();

        // -------- Phase D: weighted mean over valid paths + scatter --------
        if (t < DD) {
            float o = 0.f;
            int nv = 0;
            #pragma unroll
            for (int p = 0; p < PP; p++) {
                o += sWgt[p] * sAgg[p * DD + t];
                nv += sVal[p];
            }
            out[__ldg(sids + s) * DD + t] = o / (float)(nv > 0 ? nv : 1);
        }
        __syncthreads();
    }
}

extern "C" void kernel_launch(void* const* d_in, const int* in_sizes, int n_in,
                              void* d_out, int out_size) {
    const float* E   = (const float*)d_in[0];
    const float* W1  = (const float*)d_in[1];
    const float* b1  = (const float*)d_in[2];
    const float* W2  = (const float*)d_in[3];
    const float* b2  = (const float*)d_in[4];
    const int*   sid = (const int*)d_in[5];
    const int*   eid = (const int*)d_in[6];
    const void*  msk = d_in[7];
    float* out = (float*)d_out;

    const int S = in_sizes[5];

    // Output is poisoned: zero it (rows not in sparse_ids must be 0).
    cudaMemsetAsync(d_out, 0, (size_t)out_size * sizeof(float), 0);

    // Detect mask dtype (deterministic, data-dependent but fixed inputs).
    detect_mask_kernel<<<1, 1024>>>((const unsigned int*)msk);

    static const int SMEM_BYTES = SMEM_FLOATS * 4; // 49792 > 48K -> opt-in
    cudaFuncSetAttribute(pga_kernel, cudaFuncAttributeMaxDynamicSharedMemorySize,
                         SMEM_BYTES);

    int grid = 1024;
    if (grid > S) grid = S;
    pga_kernel<<<grid, 512, SMEM_BYTES>>>(E, W1, b1, W2, b2, sid, eid, msk, out, S);
}